// round 14
// baseline (speedup 1.0000x reference)
#include <cuda_runtime.h>
#include <cstdint>
#include <cstddef>

#define NE 8
#define NC 4096
#define NM 1024
#define NH 4096
#define NO 1024

// Scratch (no allocs allowed):
__device__ float g_hbuf[(size_t)NE * NC * NH];   // h, stored tf32-pre-rounded
__device__ float g_xr [(size_t)NE * NC * NM];    // x pre-rounded
__device__ float g_w1r[(size_t)NE * NH * NM];    // fc1_w pre-rounded
__device__ float g_w2t[(size_t)NE * NO * NH];    // fc2_w transposed [O,H] + pre-rounded

static __device__ __forceinline__ uint32_t f2tf32(float f) {
    uint32_t u;
    asm("cvt.rna.tf32.f32 %0, %1;" : "=r"(u) : "f"(f));
    return u;
}
static __device__ __forceinline__ void cpa16(uint32_t dst, const float* src) {
    asm volatile("cp.async.cg.shared.global [%0], [%1], 16;" :: "r"(dst), "l"(src));
}

// Elementwise tf32 pre-round (rna)
__global__ __launch_bounds__(256)
void round_tf32_kernel(const float4* __restrict__ in, float4* __restrict__ out, size_t n4) {
    size_t i = (size_t)blockIdx.x * blockDim.x + threadIdx.x;
    size_t stride = (size_t)gridDim.x * blockDim.x;
    for (; i < n4; i += stride) {
        float4 v = in[i];
        float4 o;
        o.x = __uint_as_float(f2tf32(v.x));
        o.y = __uint_as_float(f2tf32(v.y));
        o.z = __uint_as_float(f2tf32(v.z));
        o.w = __uint_as_float(f2tf32(v.w));
        out[i] = o;
    }
}

// fc2_w [E,H,O] -> [E,O,H], tf32-rounded (so GEMM2 B is K-major like GEMM1)
__global__ __launch_bounds__(256)
void transpose_round_w2(const float* __restrict__ w2, float* __restrict__ w2t) {
    __shared__ float tile[32][33];
    const int e = blockIdx.z;
    const float* src = w2 + (size_t)e * NH * NO;
    float* dst = w2t + (size_t)e * NO * NH;
    const int o0 = blockIdx.x * 32, h0 = blockIdx.y * 32;
    const int tx = threadIdx.x, ty = threadIdx.y;
    #pragma unroll
    for (int i = ty; i < 32; i += 8)
        tile[i][tx] = src[(size_t)(h0 + i) * NO + o0 + tx];
    __syncthreads();
    #pragma unroll
    for (int i = ty; i < 32; i += 8)
        dst[(size_t)(o0 + i) * NH + h0 + tx] =
            __uint_as_float(f2tf32(tile[tx][i]));
}

// D[row,n] = sum_k A[row,k]*B[n,k] + bias[n]  (RELU_CVT: relu + tf32-round output)
// A,B K-major, values already tf32-rounded. CTA tile 128x128, K-step 32,
// double-buffered cp.async. 128 threads = 4 warps in 2(m)x2(n), warp tile 64x64.
//
// k-relabel trick: within each m16n8k8, position v -> physical k = kk+2v,
// position v+4 -> kk+2v+1 (same map for A and B => identical sum). So each
// thread's fragment pair is CONTIGUOUS: one LDS.64 per A-row-pair / B-col.
// Row stride 40 words: LDS.64 16-lane phase banks = 8u+2v, bijective mod 32
// => conflict-free. Frag-load instruction count halves vs v4.
template <bool RELU_CVT>
__global__ __launch_bounds__(128, 2)
void ffn_gemm_v5(const float* __restrict__ Ag, const float* __restrict__ Bg,
                 const float* __restrict__ biasg, float* __restrict__ Dg,
                 int K, int Ntot,
                 size_t sA, size_t sB, size_t sBias, size_t sD)
{
    extern __shared__ uint32_t smdyn[];
    constexpr int RS = 40;          // row stride in words
    constexpr int AW = 128 * RS;    // 5120 words per buffer
    uint32_t* Asb[2] = { smdyn,          smdyn + AW };
    uint32_t* Bsb[2] = { smdyn + 2 * AW, smdyn + 3 * AW };

    const int tid  = threadIdx.x;
    const int lane = tid & 31;
    const int warp = tid >> 5;
    const int wm   = warp >> 1;   // 0..1 -> m offset wm*64
    const int wn   = warp & 1;    // 0..1 -> n offset wn*64
    const int u    = lane >> 2;   // 0..7
    const int v    = lane & 3;    // 0..3

    const int e  = blockIdx.z;
    const int mb = blockIdx.y * 128;
    const int nb = blockIdx.x * 128;

    const float* A    = Ag + (size_t)e * sA;
    const float* B    = Bg + (size_t)e * sB;
    const float* bias = biasg + (size_t)e * sBias + nb;
    float*       D    = Dg + (size_t)e * sD;

    float acc[4][8][4];
    #pragma unroll
    for (int a = 0; a < 4; a++)
        #pragma unroll
        for (int b = 0; b < 8; b++)
            #pragma unroll
            for (int c = 0; c < 4; c++)
                acc[a][b][c] = 0.0f;

    // Staging: 128 threads, 8 rows each of A and B per k-tile (16 cp.async/thread)
    const int r0 = tid >> 3;           // 0..15
    const int c4 = (tid & 7) << 2;     // {0,4,...,28}
    const float* Apt = A + (size_t)(mb + r0) * K + c4;
    const float* Bpt = B + (size_t)(nb + r0) * K + c4;

    const int T = K >> 5;

    auto stage = [&](int b, int k0) {
        uint32_t abase = (uint32_t)__cvta_generic_to_shared(Asb[b]);
        uint32_t bbase = (uint32_t)__cvta_generic_to_shared(Bsb[b]);
        #pragma unroll
        for (int i = 0; i < 8; i++)
            cpa16(abase + ((i * 16 + r0) * RS + c4) * 4, Apt + (size_t)(i * 16) * K + k0);
        #pragma unroll
        for (int i = 0; i < 8; i++)
            cpa16(bbase + ((i * 16 + r0) * RS + c4) * 4, Bpt + (size_t)(i * 16) * K + k0);
    };

    // ---- prologue ----
    stage(0, 0);
    asm volatile("cp.async.commit_group;" ::: "memory");
    asm volatile("cp.async.wait_group 0;" ::: "memory");
    __syncthreads();

    // ---- mainloop ----
    for (int t = 0; t < T; t++) {
        const int p = t & 1;
        if (t + 1 < T) {
            stage(1 - p, (t + 1) << 5);
            asm volatile("cp.async.commit_group;" ::: "memory");
        }

        const uint32_t* __restrict__ As = Asb[p];
        const uint32_t* __restrict__ Bs = Bsb[p];
        #pragma unroll
        for (int kk = 0; kk < 32; kk += 8) {
            // One LDS.64 per pair: {a0,a2} rows u, {a1,a3} rows u+8, {b0,b1}.
            uint2 a0[4], a1[4];
            uint2 bf[8];
            #pragma unroll
            for (int tm = 0; tm < 4; tm++) {
                const int ia = (wm * 64 + tm * 16 + u) * RS + kk + 2 * v;
                a0[tm] = *(const uint2*)&As[ia];
                a1[tm] = *(const uint2*)&As[ia + 8 * RS];
            }
            #pragma unroll
            for (int tn = 0; tn < 8; tn++) {
                const int ib = (wn * 64 + tn * 8 + u) * RS + kk + 2 * v;
                bf[tn] = *(const uint2*)&Bs[ib];
            }
            #pragma unroll
            for (int tm = 0; tm < 4; tm++)
                #pragma unroll
                for (int tn = 0; tn < 8; tn++) {
                    float* c = acc[tm][tn];
                    asm volatile(
                        "mma.sync.aligned.m16n8k8.row.col.f32.tf32.tf32.f32 "
                        "{%0,%1,%2,%3}, {%4,%5,%6,%7}, {%8,%9}, {%0,%1,%2,%3};\n"
                        : "+f"(c[0]), "+f"(c[1]), "+f"(c[2]), "+f"(c[3])
                        : "r"(a0[tm].x), "r"(a1[tm].x), "r"(a0[tm].y), "r"(a1[tm].y),
                          "r"(bf[tn].x), "r"(bf[tn].y));
                }
        }

        if (t + 1 < T)
            asm volatile("cp.async.wait_group 0;" ::: "memory");
        __syncthreads();
    }

    // ---- epilogue ----
    #pragma unroll
    for (int tm = 0; tm < 4; tm++) {
        const int row = mb + wm * 64 + tm * 16 + u;
        #pragma unroll
        for (int tn = 0; tn < 8; tn++) {
            const int lc = wn * 64 + tn * 8 + 2 * v;
            const float2 bv = *(const float2*)&bias[lc];
            float x0 = acc[tm][tn][0] + bv.x;
            float x1 = acc[tm][tn][1] + bv.y;
            float x2 = acc[tm][tn][2] + bv.x;
            float x3 = acc[tm][tn][3] + bv.y;
            if (RELU_CVT) {
                x0 = __uint_as_float(f2tf32(fmaxf(x0, 0.0f)));
                x1 = __uint_as_float(f2tf32(fmaxf(x1, 0.0f)));
                x2 = __uint_as_float(f2tf32(fmaxf(x2, 0.0f)));
                x3 = __uint_as_float(f2tf32(fmaxf(x3, 0.0f)));
            }
            *(float2*)&D[(size_t)row * Ntot + nb + lc]       = make_float2(x0, x1);
            *(float2*)&D[(size_t)(row + 8) * Ntot + nb + lc] = make_float2(x2, x3);
        }
    }
}

extern "C" void kernel_launch(void* const* d_in, const int* in_sizes, int n_in,
                              void* d_out, int out_size)
{
    const float* x     = (const float*)d_in[0];   // [E, C, M]
    const float* fc1_w = (const float*)d_in[1];   // [E, H, M]  (K-major)
    const float* fc1_b = (const float*)d_in[2];   // [E, H]
    const float* fc2_w = (const float*)d_in[3];   // [E, H, O]  -> transpose to [E,O,H]
    const float* fc2_b = (const float*)d_in[4];   // [E, O]
    float* out = (float*)d_out;                   // [E, C, O]

    float *hb = nullptr, *xr = nullptr, *w1r = nullptr, *w2t = nullptr;
    cudaGetSymbolAddress((void**)&hb,  g_hbuf);
    cudaGetSymbolAddress((void**)&xr,  g_xr);
    cudaGetSymbolAddress((void**)&w1r, g_w1r);
    cudaGetSymbolAddress((void**)&w2t, g_w2t);

    // 0) pre-round x / fc1_w; transpose+round fc2_w
    round_tf32_kernel<<<4096, 256>>>((const float4*)x,     (float4*)xr,
                                     (size_t)NE * NC * NM / 4);
    round_tf32_kernel<<<4096, 256>>>((const float4*)fc1_w, (float4*)w1r,
                                     (size_t)NE * NH * NM / 4);
    transpose_round_w2<<<dim3(NO / 32, NH / 32, NE), dim3(32, 8)>>>(fc2_w, w2t);

    const int SMB = 4 * 128 * 40 * 4;   // 81,920 B (A0,A1,B0,B1)
    cudaFuncSetAttribute((const void*)ffn_gemm_v5<true>,
                         cudaFuncAttributeMaxDynamicSharedMemorySize, SMB);
    cudaFuncSetAttribute((const void*)ffn_gemm_v5<false>,
                         cudaFuncAttributeMaxDynamicSharedMemorySize, SMB);

    // 1) h = relu(x @ fc1_w^T + b1), stored tf32-rounded   (M=C, N=H, K=M)
    ffn_gemm_v5<true><<<dim3(NH / 128, NC / 128, NE), 128, SMB>>>(
        xr, w1r, fc1_b, hb,
        NM, NH,
        (size_t)NC * NM, (size_t)NH * NM, (size_t)NH, (size_t)NC * NH);

    // 2) y = h @ w2t^T + b2                                (M=C, N=O, K=H)
    ffn_gemm_v5<false><<<dim3(NO / 128, NC / 128, NE), 128, SMB>>>(
        hb, w2t, fc2_b, out,
        NH, NO,
        (size_t)NC * NH, (size_t)NO * NH, (size_t)NO, (size_t)NC * NO);
}

// round 16
// speedup vs baseline: 1.0011x; 1.0011x over previous
#include <cuda_runtime.h>
#include <cstdint>
#include <cstddef>

#define NE 8
#define NC 4096
#define NM 1024
#define NH 4096
#define NO 1024

// Scratch (no allocs allowed):
__device__ float g_hbuf[(size_t)NE * NC * NH];   // h, stored tf32-pre-rounded
__device__ float g_xr [(size_t)NE * NC * NM];    // x pre-rounded
__device__ float g_w1r[(size_t)NE * NH * NM];    // fc1_w pre-rounded
__device__ float g_w2t[(size_t)NE * NO * NH];    // fc2_w transposed [O,H] + pre-rounded

static __device__ __forceinline__ uint32_t f2tf32(float f) {
    uint32_t u;
    asm("cvt.rna.tf32.f32 %0, %1;" : "=r"(u) : "f"(f));
    return u;
}
static __device__ __forceinline__ void cpa16(uint32_t dst, const float* src) {
    asm volatile("cp.async.cg.shared.global [%0], [%1], 16;" :: "r"(dst), "l"(src));
}
// ldmatrix x4: four 8x8-b16 matrices == four 8row x 4word fp32 tiles.
// Thread(lane) gets word lane%4 of row lane/4 of each tile == tf32 frag layout.
static __device__ __forceinline__ void ldsm4(uint32_t& r0, uint32_t& r1,
                                             uint32_t& r2, uint32_t& r3, uint32_t addr) {
    asm volatile("ldmatrix.sync.aligned.m8n8.x4.shared.b16 {%0,%1,%2,%3}, [%4];"
                 : "=r"(r0), "=r"(r1), "=r"(r2), "=r"(r3) : "r"(addr));
}

// Elementwise tf32 pre-round (rna)
__global__ __launch_bounds__(256)
void round_tf32_kernel(const float4* __restrict__ in, float4* __restrict__ out, size_t n4) {
    size_t i = (size_t)blockIdx.x * blockDim.x + threadIdx.x;
    size_t stride = (size_t)gridDim.x * blockDim.x;
    for (; i < n4; i += stride) {
        float4 v = in[i];
        float4 o;
        o.x = __uint_as_float(f2tf32(v.x));
        o.y = __uint_as_float(f2tf32(v.y));
        o.z = __uint_as_float(f2tf32(v.z));
        o.w = __uint_as_float(f2tf32(v.w));
        out[i] = o;
    }
}

// fc2_w [E,H,O] -> [E,O,H], tf32-rounded (so GEMM2 B is K-major like GEMM1)
__global__ __launch_bounds__(256)
void transpose_round_w2(const float* __restrict__ w2, float* __restrict__ w2t) {
    __shared__ float tile[32][33];
    const int e = blockIdx.z;
    const float* src = w2 + (size_t)e * NH * NO;
    float* dst = w2t + (size_t)e * NO * NH;
    const int o0 = blockIdx.x * 32, h0 = blockIdx.y * 32;
    const int tx = threadIdx.x, ty = threadIdx.y;
    #pragma unroll
    for (int i = ty; i < 32; i += 8)
        tile[i][tx] = src[(size_t)(h0 + i) * NO + o0 + tx];
    __syncthreads();
    #pragma unroll
    for (int i = ty; i < 32; i += 8)
        dst[(size_t)(o0 + i) * NH + h0 + tx] =
            __uint_as_float(f2tf32(tile[tx][i]));
}

// D[row,n] = sum_k A[row,k]*B[n,k] + bias[n]  (RELU_CVT: relu + tf32-round output)
// A,B K-major, tf32-pre-rounded. CTA 128x128, K-step 32, double-buffered cp.async.
// 128 threads = 4 warps 2(m)x2(n), warp tile 64x64. Fragments via LDSM.x4:
// 8 ldmatrix per kk-step replace 32 LDS.32 (shorter issue block + fewer SB arms).
// Stride 36: each matrix's 8 rows start at banks 4r (16B each) -> all 32 banks
// exactly once, conflict-free.
template <bool RELU_CVT>
__global__ __launch_bounds__(128, 2)
void ffn_gemm_v6(const float* __restrict__ Ag, const float* __restrict__ Bg,
                 const float* __restrict__ biasg, float* __restrict__ Dg,
                 int K, int Ntot,
                 size_t sA, size_t sB, size_t sBias, size_t sD)
{
    extern __shared__ uint32_t smdyn[];
    constexpr int RS = 36;         // row stride in words
    constexpr int AW = 128 * RS;   // words per buffer
    uint32_t* Asb[2] = { smdyn,          smdyn + AW };
    uint32_t* Bsb[2] = { smdyn + 2 * AW, smdyn + 3 * AW };

    const int tid  = threadIdx.x;
    const int lane = tid & 31;
    const int warp = tid >> 5;
    const int wm   = warp >> 1;   // 0..1 -> m offset wm*64
    const int wn   = warp & 1;    // 0..1 -> n offset wn*64
    const int u    = lane >> 2;   // 0..7
    const int v    = lane & 3;    // 0..3

    const int e  = blockIdx.z;
    const int mb = blockIdx.y * 128;
    const int nb = blockIdx.x * 128;

    const float* A    = Ag + (size_t)e * sA;
    const float* B    = Bg + (size_t)e * sB;
    const float* bias = biasg + (size_t)e * sBias + nb;
    float*       D    = Dg + (size_t)e * sD;

    float acc[4][8][4];
    #pragma unroll
    for (int a = 0; a < 4; a++)
        #pragma unroll
        for (int b = 0; b < 8; b++)
            #pragma unroll
            for (int c = 0; c < 4; c++)
                acc[a][b][c] = 0.0f;

    // Staging: 128 threads, 8 rows each of A and B per k-tile (16 cp.async/thread)
    const int r0 = tid >> 3;           // 0..15
    const int c4 = (tid & 7) << 2;     // {0,4,...,28}
    const float* Apt = A + (size_t)(mb + r0) * K + c4;
    const float* Bpt = B + (size_t)(nb + r0) * K + c4;

    const int T = K >> 5;

    auto stage = [&](int b, int k0) {
        uint32_t abase = (uint32_t)__cvta_generic_to_shared(Asb[b]);
        uint32_t bbase = (uint32_t)__cvta_generic_to_shared(Bsb[b]);
        #pragma unroll
        for (int i = 0; i < 8; i++)
            cpa16(abase + ((i * 16 + r0) * RS + c4) * 4, Apt + (size_t)(i * 16) * K + k0);
        #pragma unroll
        for (int i = 0; i < 8; i++)
            cpa16(bbase + ((i * 16 + r0) * RS + c4) * 4, Bpt + (size_t)(i * 16) * K + k0);
    };

    // LDSM per-lane address offsets (in words, relative to buffer base).
    // A tm-group: g=lane>>3: m0 rows+0 col+0 | m1 rows+8 col+0 | m2 rows+0 col+4 | m3 rows+8 col+4
    const int ag = lane >> 3, ar = lane & 7;
    const int a_row = (ag & 1) * 8 + ar;         // row within 16-row tm tile
    const int a_col = (ag >> 1) * 4;             // word col 0 or 4
    // B pair j (tn=2j,2j+1): m0 tn rows col0 | m1 tn rows col4 | m2 tn+1 rows col0 | m3 tn+1 col4
    const int b_row = (ag >> 1) * 8 + ar;        // row within 16-row pair
    const int b_col = (ag & 1) * 4;

    uint32_t aoff[4], boff[4];
    #pragma unroll
    for (int tm = 0; tm < 4; tm++)
        aoff[tm] = ((wm * 64 + tm * 16 + a_row) * RS + a_col) * 4;
    #pragma unroll
    for (int j = 0; j < 4; j++)
        boff[j] = ((wn * 64 + j * 16 + b_row) * RS + b_col) * 4;

    // ---- prologue ----
    stage(0, 0);
    asm volatile("cp.async.commit_group;" ::: "memory");
    asm volatile("cp.async.wait_group 0;" ::: "memory");
    __syncthreads();

    // ---- mainloop ----
    for (int t = 0; t < T; t++) {
        const int p = t & 1;
        if (t + 1 < T) {
            stage(1 - p, (t + 1) << 5);
            asm volatile("cp.async.commit_group;" ::: "memory");
        }

        const uint32_t abase = (uint32_t)__cvta_generic_to_shared(Asb[p]);
        const uint32_t bbase = (uint32_t)__cvta_generic_to_shared(Bsb[p]);
        #pragma unroll
        for (int kk = 0; kk < 32; kk += 8) {
            uint32_t af[4][4];
            uint32_t bf[8][2];
            #pragma unroll
            for (int tm = 0; tm < 4; tm++)
                ldsm4(af[tm][0], af[tm][1], af[tm][2], af[tm][3],
                      abase + aoff[tm] + kk * 4);
            #pragma unroll
            for (int j = 0; j < 4; j++)
                ldsm4(bf[2 * j][0], bf[2 * j][1], bf[2 * j + 1][0], bf[2 * j + 1][1],
                      bbase + boff[j] + kk * 4);
            #pragma unroll
            for (int tm = 0; tm < 4; tm++)
                #pragma unroll
                for (int tn = 0; tn < 8; tn++) {
                    float* c = acc[tm][tn];
                    asm volatile(
                        "mma.sync.aligned.m16n8k8.row.col.f32.tf32.tf32.f32 "
                        "{%0,%1,%2,%3}, {%4,%5,%6,%7}, {%8,%9}, {%0,%1,%2,%3};\n"
                        : "+f"(c[0]), "+f"(c[1]), "+f"(c[2]), "+f"(c[3])
                        : "r"(af[tm][0]), "r"(af[tm][1]), "r"(af[tm][2]), "r"(af[tm][3]),
                          "r"(bf[tn][0]), "r"(bf[tn][1]));
                }
        }

        if (t + 1 < T)
            asm volatile("cp.async.wait_group 0;" ::: "memory");
        __syncthreads();
    }

    // ---- epilogue ----
    #pragma unroll
    for (int tm = 0; tm < 4; tm++) {
        const int row = mb + wm * 64 + tm * 16 + u;
        #pragma unroll
        for (int tn = 0; tn < 8; tn++) {
            const int lc = wn * 64 + tn * 8 + 2 * v;
            const float2 bv = *(const float2*)&bias[lc];
            float x0 = acc[tm][tn][0] + bv.x;
            float x1 = acc[tm][tn][1] + bv.y;
            float x2 = acc[tm][tn][2] + bv.x;
            float x3 = acc[tm][tn][3] + bv.y;
            if (RELU_CVT) {
                x0 = __uint_as_float(f2tf32(fmaxf(x0, 0.0f)));
                x1 = __uint_as_float(f2tf32(fmaxf(x1, 0.0f)));
                x2 = __uint_as_float(f2tf32(fmaxf(x2, 0.0f)));
                x3 = __uint_as_float(f2tf32(fmaxf(x3, 0.0f)));
            }
            *(float2*)&D[(size_t)row * Ntot + nb + lc]       = make_float2(x0, x1);
            *(float2*)&D[(size_t)(row + 8) * Ntot + nb + lc] = make_float2(x2, x3);
        }
    }
}

extern "C" void kernel_launch(void* const* d_in, const int* in_sizes, int n_in,
                              void* d_out, int out_size)
{
    const float* x     = (const float*)d_in[0];   // [E, C, M]
    const float* fc1_w = (const float*)d_in[1];   // [E, H, M]  (K-major)
    const float* fc1_b = (const float*)d_in[2];   // [E, H]
    const float* fc2_w = (const float*)d_in[3];   // [E, H, O]  -> transpose to [E,O,H]
    const float* fc2_b = (const float*)d_in[4];   // [E, O]
    float* out = (float*)d_out;                   // [E, C, O]

    float *hb = nullptr, *xr = nullptr, *w1r = nullptr, *w2t = nullptr;
    cudaGetSymbolAddress((void**)&hb,  g_hbuf);
    cudaGetSymbolAddress((void**)&xr,  g_xr);
    cudaGetSymbolAddress((void**)&w1r, g_w1r);
    cudaGetSymbolAddress((void**)&w2t, g_w2t);

    // 0) pre-round x / fc1_w; transpose+round fc2_w
    round_tf32_kernel<<<4096, 256>>>((const float4*)x,     (float4*)xr,
                                     (size_t)NE * NC * NM / 4);
    round_tf32_kernel<<<4096, 256>>>((const float4*)fc1_w, (float4*)w1r,
                                     (size_t)NE * NH * NM / 4);
    transpose_round_w2<<<dim3(NO / 32, NH / 32, NE), dim3(32, 8)>>>(fc2_w, w2t);

    const int SMB = 4 * 128 * 36 * 4;   // 73,728 B (A0,A1,B0,B1)
    cudaFuncSetAttribute((const void*)ffn_gemm_v6<true>,
                         cudaFuncAttributeMaxDynamicSharedMemorySize, SMB);
    cudaFuncSetAttribute((const void*)ffn_gemm_v6<false>,
                         cudaFuncAttributeMaxDynamicSharedMemorySize, SMB);

    // 1) h = relu(x @ fc1_w^T + b1), stored tf32-rounded   (M=C, N=H, K=M)
    ffn_gemm_v6<true><<<dim3(NH / 128, NC / 128, NE), 128, SMB>>>(
        xr, w1r, fc1_b, hb,
        NM, NH,
        (size_t)NC * NM, (size_t)NH * NM, (size_t)NH, (size_t)NC * NH);

    // 2) y = h @ w2t^T + b2                                (M=C, N=O, K=H)
    ffn_gemm_v6<false><<<dim3(NO / 128, NC / 128, NE), 128, SMB>>>(
        hb, w2t, fc2_b, out,
        NH, NO,
        (size_t)NC * NH, (size_t)NO * NH, (size_t)NO, (size_t)NC * NO);
}